// round 1
// baseline (speedup 1.0000x reference)
#include <cuda_runtime.h>

// Problem constants (fixed by the dataset)
#define N_NODES 12288
#define F_DIMV  512
#define H_DIMV  64
#define E_MAX   393216

// ---------------- scratch (no allocations allowed) ----------------
__device__ float g_m[N_NODES * H_DIMV];      // transformed feats pre-aggregation
__device__ float g_x[N_NODES * H_DIMV];      // encoder layer 1 out
__device__ float g_x2[N_NODES * H_DIMV];     // encoder layer 2 out
__device__ float g_xa[N_NODES * H_DIMV];     // attr decoder hidden
__device__ float g_aggxa[N_NODES * H_DIMV];  // agg(xa)
__device__ float g_s[N_NODES * H_DIMV];      // structure embedding
__device__ int   g_deg[N_NODES];
__device__ int   g_off[N_NODES + 1];
__device__ int   g_cur[N_NODES];
__device__ int   g_csr[E_MAX];

// ---------------- CSR build ----------------
__global__ void k_zero_deg() {
    int i = blockIdx.x * blockDim.x + threadIdx.x;
    if (i < N_NODES) g_deg[i] = 0;
}

__global__ void k_count(const int* __restrict__ ei, int E) {
    int e = blockIdx.x * blockDim.x + threadIdx.x;
    if (e < E) atomicAdd(&g_deg[ei[E + e]], 1);
}

// Single-block exclusive scan over 12288 counts (1024 threads x 12 items)
__global__ void k_scan() {
    __shared__ int ts[1024];
    int t = threadIdx.x;
    int base = t * 12;
    int loc[12];
    int s = 0;
#pragma unroll
    for (int i = 0; i < 12; i++) { loc[i] = s; s += g_deg[base + i]; }
    ts[t] = s;
    __syncthreads();
    for (int d = 1; d < 1024; d <<= 1) {
        int v = ts[t];
        int add = (t >= d) ? ts[t - d] : 0;
        __syncthreads();
        ts[t] = v + add;
        __syncthreads();
    }
    int prev = (t == 0) ? 0 : ts[t - 1];
#pragma unroll
    for (int i = 0; i < 12; i++) {
        int o = prev + loc[i];
        g_off[base + i] = o;
        g_cur[base + i] = o;
    }
    if (t == 1023) g_off[N_NODES] = ts[1023];
}

__global__ void k_fill(const int* __restrict__ ei, int E) {
    int e = blockIdx.x * blockDim.x + threadIdx.x;
    if (e < E) {
        int dst = ei[E + e];
        int p = atomicAdd(&g_cur[dst], 1);
        g_csr[p] = ei[e];
    }
}

// ---------------- edge aggregation: out[n] = relu(sum_{e: dst=n} m[src_e] + b)
// one warp per node, float2 per lane (64 dims). m is L2-resident (3MB).
__global__ void k_agg(const float* __restrict__ m, const float* __restrict__ bias,
                      float* __restrict__ out, int relu) {
    int w = (blockIdx.x * blockDim.x + threadIdx.x) >> 5;
    if (w >= N_NODES) return;
    int lane = threadIdx.x & 31;
    int e = g_off[w], e1 = g_off[w + 1];
    float ax = 0.f, ay = 0.f;
    for (; e + 1 < e1; e += 2) {
        int sa = g_csr[e], sb = g_csr[e + 1];
        float2 va = *(const float2*)(m + sa * 64 + 2 * lane);
        float2 vb = *(const float2*)(m + sb * 64 + 2 * lane);
        ax += va.x; ay += va.y;
        ax += vb.x; ay += vb.y;
    }
    if (e < e1) {
        float2 va = *(const float2*)(m + g_csr[e] * 64 + 2 * lane);
        ax += va.x; ay += va.y;
    }
    if (bias) { ax += bias[2 * lane]; ay += bias[2 * lane + 1]; }
    if (relu) { ax = fmaxf(ax, 0.f); ay = fmaxf(ay, 0.f); }
    float2 r; r.x = ax; r.y = ay;
    *(float2*)(out + w * 64 + 2 * lane) = r;
}

// ---------------- generic GEMM: Y[N,P] = X[N,K] @ W[K,P] (+bias, relu)
// 128x64 output tile per block, 256 threads, 8x4 per thread (interleaved lanes),
// K consumed in chunks of 32 through shared memory.
__global__ void __launch_bounds__(256)
k_gemm(const float* __restrict__ X, const float* __restrict__ W,
       const float* __restrict__ bias, float* __restrict__ Y,
       int K, int P, int relu) {
    __shared__ float As[32 * 129];   // [k][row], padded
    __shared__ float Bs[32 * 64];    // [k][col]
    int tid = threadIdx.x;
    int tx = tid & 15, ty = tid >> 4;
    int rbase = blockIdx.x * 128, cbase = blockIdx.y * 64;

    float acc[8][4];
#pragma unroll
    for (int i = 0; i < 8; i++)
#pragma unroll
        for (int j = 0; j < 4; j++) acc[i][j] = 0.f;

    for (int kc = 0; kc < K; kc += 32) {
        __syncthreads();
#pragma unroll
        for (int i = 0; i < 16; i++) {                 // 4096 A floats
            int idx = tid + i * 256;
            int k = idx & 31, row = idx >> 5;
            As[k * 129 + row] = X[(size_t)(rbase + row) * K + kc + k];
        }
#pragma unroll
        for (int i = 0; i < 8; i++) {                  // 2048 B floats
            int idx = tid + i * 256;
            int k = idx >> 6, c = idx & 63;
            Bs[k * 64 + c] = W[(size_t)(kc + k) * P + cbase + c];
        }
        __syncthreads();
#pragma unroll
        for (int k = 0; k < 32; k++) {
            float a[8], b[4];
#pragma unroll
            for (int i = 0; i < 8; i++) a[i] = As[k * 129 + ty + i * 16];
#pragma unroll
            for (int j = 0; j < 4; j++) b[j] = Bs[k * 64 + tx + j * 16];
#pragma unroll
            for (int i = 0; i < 8; i++)
#pragma unroll
                for (int j = 0; j < 4; j++)
                    acc[i][j] = fmaf(a[i], b[j], acc[i][j]);
        }
    }

#pragma unroll
    for (int i = 0; i < 8; i++) {
        int r = rbase + ty + i * 16;
#pragma unroll
        for (int j = 0; j < 4; j++) {
            int c = cbase + tx + j * 16;
            float v = acc[i][j];
            if (bias) v += bias[c];
            if (relu) v = fmaxf(v, 0.f);
            Y[(size_t)r * P + c] = v;
        }
    }
}

// ---------------- C = S @ S^T, symmetric: compute upper-triangular block tiles,
// mirror the lower triangle through an smem transpose stage (coalesced writes).
__global__ void __launch_bounds__(256)
k_sst(const float* __restrict__ S, float* __restrict__ C) {
    int bx = blockIdx.x, by = blockIdx.y;     // bx = col tile, by = row tile
    if (by > bx) return;                      // upper triangle only
    __shared__ float sm[64 * 129];            // As | Bs, reused as Ts for mirror
    float* As = sm;                           // [32][129]
    float* Bs = sm + 32 * 129;                // [32][129]
    int tid = threadIdx.x;
    int tx = tid & 15, ty = tid >> 4;
    int rbase = by * 128, cbase = bx * 128;
    const size_t NN = (size_t)N_NODES;

    float acc[8][8];
#pragma unroll
    for (int i = 0; i < 8; i++)
#pragma unroll
        for (int j = 0; j < 8; j++) acc[i][j] = 0.f;

    for (int kc = 0; kc < 64; kc += 32) {
        __syncthreads();
#pragma unroll
        for (int i = 0; i < 16; i++) {
            int idx = tid + i * 256;
            int k = idx & 31, row = idx >> 5;
            As[k * 129 + row] = S[(size_t)(rbase + row) * 64 + kc + k];
            Bs[k * 129 + row] = S[(size_t)(cbase + row) * 64 + kc + k];
        }
        __syncthreads();
#pragma unroll
        for (int k = 0; k < 32; k++) {
            float a[8], b[8];
#pragma unroll
            for (int i = 0; i < 8; i++) a[i] = As[k * 129 + ty + i * 16];
#pragma unroll
            for (int j = 0; j < 8; j++) b[j] = Bs[k * 129 + tx + j * 16];
#pragma unroll
            for (int i = 0; i < 8; i++)
#pragma unroll
                for (int j = 0; j < 8; j++)
                    acc[i][j] = fmaf(a[i], b[j], acc[i][j]);
        }
    }

    // direct (upper) tile write: row rbase+ty+16i, col cbase+tx+16j
#pragma unroll
    for (int i = 0; i < 8; i++) {
        size_t r = (size_t)(rbase + ty + i * 16);
#pragma unroll
        for (int j = 0; j < 8; j++) {
            int c = cbase + tx + j * 16;
            C[r * NN + c] = acc[i][j];
        }
    }

    if (by == bx) return;

    // mirror (lower) tile: stage transpose through smem in two 64-col passes
    float* Ts = sm;                            // [64][129]
    for (int p = 0; p < 2; p++) {
        __syncthreads();
#pragma unroll
        for (int i = 0; i < 8; i++)
#pragma unroll
            for (int jj = 0; jj < 4; jj++) {
                int j = p * 4 + jj;
                int cl = tx + jj * 16;         // local col 0..63 within pass
                Ts[cl * 129 + ty + i * 16] = acc[i][j];
            }
        __syncthreads();
#pragma unroll
        for (int q = 0; q < 32; q++) {
            int lin = tid + q * 256;           // 8192 floats
            int r = lin & 127, cl = lin >> 7;
            C[(size_t)(cbase + p * 64 + cl) * NN + rbase + r] = Ts[cl * 129 + r];
        }
    }
}

// ---------------- launch ----------------
static float* symf(const void* sym) {
    void* p = nullptr;
    cudaGetSymbolAddress(&p, sym);
    return (float*)p;
}

extern "C" void kernel_launch(void* const* d_in, const int* in_sizes, int n_in,
                              void* d_out, int out_size) {
    const float* h   = (const float*)d_in[0];
    const int*   ei  = (const int*)d_in[1];
    const float* W1  = (const float*)d_in[2];
    const float* b1  = (const float*)d_in[3];
    const float* W2  = (const float*)d_in[4];
    const float* b2  = (const float*)d_in[5];
    const float* Wa1 = (const float*)d_in[6];
    const float* ba1 = (const float*)d_in[7];
    const float* Wa2 = (const float*)d_in[8];
    const float* ba2 = (const float*)d_in[9];
    const float* Ws  = (const float*)d_in[10];
    const float* bs  = (const float*)d_in[11];
    float* out = (float*)d_out;
    int E = in_sizes[1] / 2;

    float* m     = symf(g_m);
    float* x     = symf(g_x);
    float* x2    = symf(g_x2);
    float* xa    = symf(g_xa);
    float* aggxa = symf(g_aggxa);
    float* s     = symf(g_s);

    float* out_xhat = out + (size_t)N_NODES * (size_t)N_NODES;

    int eb = (E + 255) / 256;

    // CSR build (by dst)
    k_zero_deg<<<(N_NODES + 255) / 256, 256>>>();
    k_count<<<eb, 256>>>(ei, E);
    k_scan<<<1, 1024>>>();
    k_fill<<<eb, 256>>>(ei, E);

    // encoder layer 1: x = relu(agg(h @ W1) + b1)
    k_gemm<<<dim3(96, 1), 256>>>(h, W1, nullptr, m, 512, 64, 0);
    k_agg<<<1536, 256>>>(m, b1, x, 1);
    // encoder layer 2: x2 = relu(agg(x @ W2) + b2)
    k_gemm<<<dim3(96, 1), 256>>>(x, W2, nullptr, m, 64, 64, 0);
    k_agg<<<1536, 256>>>(m, b2, x2, 1);
    // attribute decoder hidden: xa = relu(agg(x2 @ Wa1) + ba1)
    k_gemm<<<dim3(96, 1), 256>>>(x2, Wa1, nullptr, m, 64, 64, 0);
    k_agg<<<1536, 256>>>(m, ba1, xa, 1);
    // attribute decoder out: x_hat = relu(agg(xa) @ Wa2 + ba2)   [agg/linear commute]
    k_agg<<<1536, 256>>>(xa, nullptr, aggxa, 0);
    k_gemm<<<dim3(96, 8), 256>>>(aggxa, Wa2, ba2, out_xhat, 64, 512, 1);
    // structure decoder: s = relu(agg(x2 @ Ws) + bs); struct = s @ s^T
    k_gemm<<<dim3(96, 1), 256>>>(x2, Ws, nullptr, m, 64, 64, 0);
    k_agg<<<1536, 256>>>(m, bs, s, 1);
    k_sst<<<dim3(96, 96), 256>>>(s, out);
}